// round 5
// baseline (speedup 1.0000x reference)
#include <cuda_runtime.h>
#include <math_constants.h>

// ----------------------------------------------------------------------------
// Window VQ: argmin_k ||z - c_k||^2 == argmax_k ( z.c_k - 0.5*||c_k||^2 )
// Exact fp32 via packed fma.rn.f32x2 (FFMA2).
//
// R5: codebook pre-transposed AND pre-duplicated ({b,b} ulonglong pairs) in
// global scratch -> hot loop has ZERO mov.b64 duplications: 4 broadcast A
// LDS.128 + 2 conflict-free B LDS.128 + 32 FFMA2 per k-step. BK=16,
// double-buffered cp.async staging, 2 CTAs/SM.
// ----------------------------------------------------------------------------

#define D       128
#define BM      64      // windows per block
#define BNT     256     // entries per n-tile
#define BK      16      // k per staged chunk
#define NTHR    256

typedef unsigned long long u64;

__device__ float g_cnorm[4096];
__device__ __align__(16) u64 g_cbTd[2048 * 128];   // dup-transposed codebook, 2MB

// ---------------------------------------------------------------------------
__global__ void cnorm_kernel(const float* __restrict__ cb, int K) {
    int row  = blockIdx.x * 8 + (threadIdx.x >> 5);
    int lane = threadIdx.x & 31;
    if (row < K) {
        const float4 v = reinterpret_cast<const float4*>(cb + (size_t)row * D)[lane];
        float s = v.x * v.x + v.y * v.y + v.z * v.z + v.w * v.w;
        #pragma unroll
        for (int o = 16; o; o >>= 1) s += __shfl_xor_sync(0xffffffffu, s, o);
        if (lane == 0) g_cnorm[row] = 0.5f * s;
    }
}

// g_cbTd layout: [nt][k 0..127][n 0..255] of {b,b} pairs; chunk (nt,kc) =
// 16k x 256n ulonglongs = 32KB contiguous = one cp.async staging pass.
__global__ void transpose_cb_kernel(const float* __restrict__ cb, int K) {
    const int o = blockIdx.x * NTHR + threadIdx.x;
    if (o < K * D) {
        const int n  = o & 255;
        const int k  = (o >> 8) & 127;
        const int nt = o >> 15;
        const float v = cb[((size_t)nt * 256 + n) * D + k];
        u64 d; asm("mov.b64 %0, {%1, %1};" : "=l"(d) : "r"(__float_as_uint(v)));
        g_cbTd[o] = d;
    }
}

#define FMA2(a, x, y) asm("fma.rn.f32x2 %0, %1, %2, %0;" : "+l"(a) : "l"(x), "l"(y))

__device__ __forceinline__ float u2f_lo(u64 a) {
    return __uint_as_float((unsigned)(a & 0xffffffffull));
}
__device__ __forceinline__ float u2f_hi(u64 a) {
    return __uint_as_float((unsigned)(a >> 32));
}

__device__ __forceinline__ void cp_async16(unsigned smem_addr, const void* gptr) {
    asm volatile("cp.async.cg.shared.global [%0], [%1], 16;"
                 :: "r"(smem_addr), "l"(gptr));
}

// ---------------------------------------------------------------------------
// Dynamic smem: As 8192 f (32KB) | Bs 2x4096 u64 (64KB) | Cn 2048 f (8KB) = 104KB
// ---------------------------------------------------------------------------
__global__ __launch_bounds__(NTHR, 2)
void vq_main_kernel(const float* __restrict__ ze,
                    const float* __restrict__ cb,
                    float* __restrict__ out,
                    int K) {
    extern __shared__ __align__(16) float sm[];
    float* As  = sm;                              // [k 0..127][m 0..63]
    u64*   Bsu = reinterpret_cast<u64*>(sm + 8192);  // 2 x [kk 0..15][n 0..255] dup
    float* Cn  = sm + 8192 + 16384;

    const int tid = threadIdx.x;
    const int tm  = tid >> 6;             // 0..3 : m = tm*16 .. +15
    const int tn  = tid & 63;             // n: {2tn, 2tn+1, 128+2tn, 128+2tn+1}

    // ---- stage A transposed: As[k*64 + m] = ze[m][k] ----
    {
        const float4* zsrc = reinterpret_cast<const float4*>(ze) + (size_t)blockIdx.x * (BM * 32);
        const int m  = tid & 63;
        const int qb = (tid >> 6) * 8;
        #pragma unroll
        for (int u = 0; u < 8; ++u) {
            const int kq = qb + u;
            const float4 v = __ldg(&zsrc[m * 32 + kq]);
            As[(kq * 4 + 0) * 64 + m] = v.x;
            As[(kq * 4 + 1) * 64 + m] = v.y;
            As[(kq * 4 + 2) * 64 + m] = v.z;
            As[(kq * 4 + 3) * 64 + m] = v.w;
        }
    }
    for (int i = tid; i < K; i += NTHR) Cn[i] = g_cnorm[i];

    const unsigned bs_base = (unsigned)__cvta_generic_to_shared(Bsu);

    // ---- prologue: stage chunk 0 (32KB linear) ----
    #pragma unroll
    for (int u = 0; u < 8; ++u) {
        const int off = u * 512 + tid * 2;            // u64 units, 16B per thread
        cp_async16(bs_base + off * 8, g_cbTd + off);
    }
    asm volatile("cp.async.commit_group;");
    asm volatile("cp.async.wait_group 0;");
    __syncthreads();

    u64 acc[8][4];
    #pragma unroll
    for (int i = 0; i < 8; ++i)
        #pragma unroll
        for (int j = 0; j < 4; ++j) acc[i][j] = 0ull;

    float best[16];
    int   bidx[16];
    #pragma unroll
    for (int i = 0; i < 16; ++i) { best[i] = -CUDART_INF_F; bidx[i] = 0; }

    const int nchunks = (K >> 8) * 8;     // 64 for K=2048
    for (int cc = 0; cc < nchunks; ++cc) {
        // issue next chunk's cp.async into the other buffer
        if (cc + 1 < nchunks) {
            const unsigned dst = bs_base + (((cc + 1) & 1) ? 4096u * 8u : 0u);
            const u64* src = g_cbTd + (size_t)(cc + 1) * 4096;
            #pragma unroll
            for (int u = 0; u < 8; ++u) {
                const int off = u * 512 + tid * 2;
                cp_async16(dst + off * 8, src + off);
            }
            asm volatile("cp.async.commit_group;");
        }

        const u64* Bbuf = Bsu + (cc & 1) * 4096;
        const int kc = cc & 7;

        // ---- compute: 16 k-steps, zero dup-movs ----
        #pragma unroll 8
        for (int kk = 0; kk < BK; ++kk) {
            const int k = kc * 16 + kk;
            const float* Ak = As + (k << 6) + (tm << 4);
            const ulonglong2 p01 = *reinterpret_cast<const ulonglong2*>(Ak);      // m 0,1
            const ulonglong2 p23 = *reinterpret_cast<const ulonglong2*>(Ak + 4);  // m 2,3
            const ulonglong2 p45 = *reinterpret_cast<const ulonglong2*>(Ak + 8);  // m 4,5
            const ulonglong2 p67 = *reinterpret_cast<const ulonglong2*>(Ak + 12); // m 6,7
            const ulonglong2 bl = *reinterpret_cast<const ulonglong2*>(&Bbuf[kk * 256 + 2 * tn]);
            const ulonglong2 bh = *reinterpret_cast<const ulonglong2*>(&Bbuf[kk * 256 + 128 + 2 * tn]);
            FMA2(acc[0][0], p01.x, bl.x); FMA2(acc[0][1], p01.x, bl.y);
            FMA2(acc[0][2], p01.x, bh.x); FMA2(acc[0][3], p01.x, bh.y);
            FMA2(acc[1][0], p01.y, bl.x); FMA2(acc[1][1], p01.y, bl.y);
            FMA2(acc[1][2], p01.y, bh.x); FMA2(acc[1][3], p01.y, bh.y);
            FMA2(acc[2][0], p23.x, bl.x); FMA2(acc[2][1], p23.x, bl.y);
            FMA2(acc[2][2], p23.x, bh.x); FMA2(acc[2][3], p23.x, bh.y);
            FMA2(acc[3][0], p23.y, bl.x); FMA2(acc[3][1], p23.y, bl.y);
            FMA2(acc[3][2], p23.y, bh.x); FMA2(acc[3][3], p23.y, bh.y);
            FMA2(acc[4][0], p45.x, bl.x); FMA2(acc[4][1], p45.x, bl.y);
            FMA2(acc[4][2], p45.x, bh.x); FMA2(acc[4][3], p45.x, bh.y);
            FMA2(acc[5][0], p45.y, bl.x); FMA2(acc[5][1], p45.y, bl.y);
            FMA2(acc[5][2], p45.y, bh.x); FMA2(acc[5][3], p45.y, bh.y);
            FMA2(acc[6][0], p67.x, bl.x); FMA2(acc[6][1], p67.x, bl.y);
            FMA2(acc[6][2], p67.x, bh.x); FMA2(acc[6][3], p67.x, bh.y);
            FMA2(acc[7][0], p67.y, bl.x); FMA2(acc[7][1], p67.y, bl.y);
            FMA2(acc[7][2], p67.y, bh.x); FMA2(acc[7][3], p67.y, bh.y);
        }

        // ---- epilogue per n-tile: scores + running argmax ----
        if (kc == 7) {
            const int nbase = (cc >> 3) << 8;
            const float2 cl = *reinterpret_cast<const float2*>(&Cn[nbase + 2 * tn]);
            const float2 ch = *reinterpret_cast<const float2*>(&Cn[nbase + 128 + 2 * tn]);
            #pragma unroll
            for (int i = 0; i < 8; ++i) {
                #pragma unroll
                for (int j = 0; j < 4; ++j) {
                    const float cn = (j == 0) ? cl.x : (j == 1) ? cl.y : (j == 2) ? ch.x : ch.y;
                    const int   n  = nbase + ((j & 2) ? 128 : 0) + 2 * tn + (j & 1);
                    const float s0 = u2f_lo(acc[i][j]) - cn;
                    const float s1 = u2f_hi(acc[i][j]) - cn;
                    if (s0 > best[2 * i])     { best[2 * i]     = s0; bidx[2 * i]     = n; }
                    if (s1 > best[2 * i + 1]) { best[2 * i + 1] = s1; bidx[2 * i + 1] = n; }
                    acc[i][j] = 0ull;
                }
            }
        }

        if (cc + 1 < nchunks) asm volatile("cp.async.wait_group 0;");
        __syncthreads();
    }

    // ---- cross-thread reduction: 64 candidates per window, alias onto Bs ----
    float* sred = reinterpret_cast<float*>(Bsu);          // [m 0..63][cand 0..63]
    int*   sidx = reinterpret_cast<int*>(Bsu) + 4096;
    int*   widx = reinterpret_cast<int*>(Bsu) + 8192;
    #pragma unroll
    for (int i = 0; i < 16; ++i) {
        const int m = tm * 16 + i;
        sred[m * 64 + tn] = best[i];
        sidx[m * 64 + tn] = bidx[i];
    }
    __syncthreads();
    if (tid < 64) {
        float bs = sred[tid * 64];
        int   bi = sidx[tid * 64];
        #pragma unroll 8
        for (int q = 1; q < 64; ++q) {
            const float s  = sred[tid * 64 + q];
            const int   ix = sidx[tid * 64 + q];
            if (s > bs || (s == bs && ix < bi)) { bs = s; bi = ix; }
        }
        widx[tid] = bi;
    }
    __syncthreads();

    // ---- gather winning codebook rows (L2-hot) ----
    const float4* cb4  = reinterpret_cast<const float4*>(cb);
    float4*       out4 = reinterpret_cast<float4*>(out) + (size_t)blockIdx.x * (BM * 32);
    #pragma unroll
    for (int i = 0; i < 8; ++i) {
        const int f = i * 256 + tid;
        const int w = f >> 5, c = f & 31;
        out4[f] = __ldg(&cb4[(size_t)widx[w] * 32 + c]);
    }
}

// ---------------------------------------------------------------------------
extern "C" void kernel_launch(void* const* d_in, const int* in_sizes, int n_in,
                              void* d_out, int out_size) {
    const float* ze = (const float*)d_in[0];
    const float* cb = (const float*)d_in[1];
    float* out = (float*)d_out;

    const int M = in_sizes[0] / D;   // 65536
    const int K = in_sizes[1] / D;   // 2048

    const int smem_bytes = (8192 + 2048) * 4 + 4096 * 2 * 8;   // 104 KB
    cudaFuncSetAttribute(vq_main_kernel, cudaFuncAttributeMaxDynamicSharedMemorySize,
                         smem_bytes);

    cnorm_kernel<<<(K + 7) / 8, NTHR>>>(cb, K);
    transpose_cb_kernel<<<(K * D + NTHR - 1) / NTHR, NTHR>>>(cb, K);
    vq_main_kernel<<<M / BM, NTHR, smem_bytes>>>(ze, cb, out, K);
}

// round 6
// speedup vs baseline: 1.0164x; 1.0164x over previous
#include <cuda_runtime.h>
#include <math_constants.h>

// ----------------------------------------------------------------------------
// Window VQ: argmin_k ||z - c_k||^2 == argmax_k ( z.c_k - 0.5*||c_k||^2 )
// Exact fp32 via packed fma.rn.f32x2 (FFMA2).
//
// R6: A pre-DUPLICATED in smem (written once, no streaming cost) + n-pair
// accumulators so streamed B is consumed as natural f32x2: ZERO dup-movs in
// the hot loop. B staged non-duplicated via TRIPLE-buffered cp.async with
// wait_group 1 (latency fully hidden). cnorm via __ldg in epilogue.
// Block 64m x 256n, thread tile 8m x 8n, 2 CTAs/SM.
// ----------------------------------------------------------------------------

#define D       128
#define BM      64
#define BNT     256
#define BK      16
#define NTHR    256

typedef unsigned long long u64;

__device__ float g_cnorm[4096];
__device__ __align__(16) float g_cbT[2048 * 128];   // transposed codebook, 1MB

// ---------------------------------------------------------------------------
__global__ void cnorm_kernel(const float* __restrict__ cb, int K) {
    int row  = blockIdx.x * 8 + (threadIdx.x >> 5);
    int lane = threadIdx.x & 31;
    if (row < K) {
        const float4 v = reinterpret_cast<const float4*>(cb + (size_t)row * D)[lane];
        float s = v.x * v.x + v.y * v.y + v.z * v.z + v.w * v.w;
        #pragma unroll
        for (int o = 16; o; o >>= 1) s += __shfl_xor_sync(0xffffffffu, s, o);
        if (lane == 0) g_cnorm[row] = 0.5f * s;
    }
}

// g_cbT layout: [nt][k 0..127][n 0..255]; chunk (nt,kc) = 16k x 256n floats
// = 16KB contiguous = one cp.async staging pass.
__global__ void transpose_cb_kernel(const float* __restrict__ cb, int K) {
    const int o = blockIdx.x * NTHR + threadIdx.x;
    if (o < K * D) {
        const int n  = o & 255;
        const int k  = (o >> 8) & 127;
        const int nt = o >> 15;
        g_cbT[o] = cb[((size_t)nt * 256 + n) * D + k];
    }
}

#define FMA2(a, x, y) asm("fma.rn.f32x2 %0, %1, %2, %0;" : "+l"(a) : "l"(x), "l"(y))

__device__ __forceinline__ float u2f_lo(u64 a) {
    return __uint_as_float((unsigned)(a & 0xffffffffull));
}
__device__ __forceinline__ float u2f_hi(u64 a) {
    return __uint_as_float((unsigned)(a >> 32));
}

__device__ __forceinline__ void cp_async16(unsigned smem_addr, const void* gptr) {
    asm volatile("cp.async.cg.shared.global [%0], [%1], 16;"
                 :: "r"(smem_addr), "l"(gptr));
}

// ---------------------------------------------------------------------------
// Dynamic smem: As-dup 8192 u64 (64KB) | Bs 3 x 4096 f (48KB)  = 112 KB
// ---------------------------------------------------------------------------
__global__ __launch_bounds__(NTHR, 2)
void vq_main_kernel(const float* __restrict__ ze,
                    const float* __restrict__ cb,
                    float* __restrict__ out,
                    int K) {
    extern __shared__ __align__(16) float sm[];
    u64*   As2 = reinterpret_cast<u64*>(sm);      // [k 0..127][m 0..63] dup pairs
    float* Bs  = sm + 16384;                      // 3 x [kk 0..15][n 0..255]

    const int tid = threadIdx.x;
    const int tm  = tid >> 5;             // 0..7 : m = tm*8 .. +7
    const int tn  = tid & 31;             // n: {4tn..4tn+3, 128+4tn..+3} per tile

    // ---- stage A duplicated: As2[k*64 + m] = {ze[m][k], ze[m][k]} ----
    {
        const float4* zsrc = reinterpret_cast<const float4*>(ze) + (size_t)blockIdx.x * (BM * 32);
        const int m  = tid & 63;
        const int qb = (tid >> 6) * 8;
        #pragma unroll
        for (int u = 0; u < 8; ++u) {
            const int kq = qb + u;
            const float4 v = __ldg(&zsrc[m * 32 + kq]);
            u64 d0, d1, d2, d3;
            asm("mov.b64 %0, {%1, %1};" : "=l"(d0) : "r"(__float_as_uint(v.x)));
            asm("mov.b64 %0, {%1, %1};" : "=l"(d1) : "r"(__float_as_uint(v.y)));
            asm("mov.b64 %0, {%1, %1};" : "=l"(d2) : "r"(__float_as_uint(v.z)));
            asm("mov.b64 %0, {%1, %1};" : "=l"(d3) : "r"(__float_as_uint(v.w)));
            As2[(kq * 4 + 0) * 64 + m] = d0;
            As2[(kq * 4 + 1) * 64 + m] = d1;
            As2[(kq * 4 + 2) * 64 + m] = d2;
            As2[(kq * 4 + 3) * 64 + m] = d3;
        }
    }

    const unsigned bs_base = (unsigned)__cvta_generic_to_shared(Bs);
    const int nchunks = (K >> 8) * 8;     // 64 for K=2048

    // ---- prologue: stage chunks 0 and 1 ----
    #pragma unroll
    for (int c0 = 0; c0 < 2; ++c0) {
        const unsigned dst = bs_base + (unsigned)c0 * 16384u;
        const float* src = g_cbT + (size_t)c0 * 4096;
        #pragma unroll
        for (int u = 0; u < 4; ++u) {
            const int off = u * 1024 + tid * 4;
            cp_async16(dst + off * 4, src + off);
        }
        asm volatile("cp.async.commit_group;");
    }

    u64 acc[8][4];
    #pragma unroll
    for (int i = 0; i < 8; ++i)
        #pragma unroll
        for (int j = 0; j < 4; ++j) acc[i][j] = 0ull;

    float best[8];
    int   bidx[8];
    #pragma unroll
    for (int i = 0; i < 8; ++i) { best[i] = -CUDART_INF_F; bidx[i] = 0; }

    for (int cc = 0; cc < nchunks; ++cc) {
        if (cc + 1 < nchunks) asm volatile("cp.async.wait_group 1;");
        else                  asm volatile("cp.async.wait_group 0;");
        __syncthreads();   // buf[cc%3] full for everyone; compute cc-1 done

        // issue chunk cc+2 into buf[(cc+2)%3] (slot last read by compute cc-1)
        if (cc + 2 < nchunks) {
            const int slot = (cc + 2) % 3;
            const unsigned dst = bs_base + (unsigned)slot * 16384u;
            const float* src = g_cbT + (size_t)(cc + 2) * 4096;
            #pragma unroll
            for (int u = 0; u < 4; ++u) {
                const int off = u * 1024 + tid * 4;
                cp_async16(dst + off * 4, src + off);
            }
            asm volatile("cp.async.commit_group;");
        }

        const float* Bbuf = Bs + (cc % 3) * 4096;
        const int kc = cc & 7;

        // ---- compute: 16 k-steps, zero dup-movs ----
        #pragma unroll 8
        for (int kk = 0; kk < BK; ++kk) {
            const int k = kc * 16 + kk;
            const u64* Ak = As2 + (k << 6) + (tm << 3);
            const ulonglong2 a01 = *reinterpret_cast<const ulonglong2*>(Ak);     // m+0,+1 dup
            const ulonglong2 a23 = *reinterpret_cast<const ulonglong2*>(Ak + 2);
            const ulonglong2 a45 = *reinterpret_cast<const ulonglong2*>(Ak + 4);
            const ulonglong2 a67 = *reinterpret_cast<const ulonglong2*>(Ak + 6);
            const ulonglong2 bl = *reinterpret_cast<const ulonglong2*>(&Bbuf[kk * 256 + 4 * tn]);
            const ulonglong2 bh = *reinterpret_cast<const ulonglong2*>(&Bbuf[kk * 256 + 128 + 4 * tn]);
            FMA2(acc[0][0], a01.x, bl.x); FMA2(acc[0][1], a01.x, bl.y);
            FMA2(acc[0][2], a01.x, bh.x); FMA2(acc[0][3], a01.x, bh.y);
            FMA2(acc[1][0], a01.y, bl.x); FMA2(acc[1][1], a01.y, bl.y);
            FMA2(acc[1][2], a01.y, bh.x); FMA2(acc[1][3], a01.y, bh.y);
            FMA2(acc[2][0], a23.x, bl.x); FMA2(acc[2][1], a23.x, bl.y);
            FMA2(acc[2][2], a23.x, bh.x); FMA2(acc[2][3], a23.x, bh.y);
            FMA2(acc[3][0], a23.y, bl.x); FMA2(acc[3][1], a23.y, bl.y);
            FMA2(acc[3][2], a23.y, bh.x); FMA2(acc[3][3], a23.y, bh.y);
            FMA2(acc[4][0], a45.x, bl.x); FMA2(acc[4][1], a45.x, bl.y);
            FMA2(acc[4][2], a45.x, bh.x); FMA2(acc[4][3], a45.x, bh.y);
            FMA2(acc[5][0], a45.y, bl.x); FMA2(acc[5][1], a45.y, bl.y);
            FMA2(acc[5][2], a45.y, bh.x); FMA2(acc[5][3], a45.y, bh.y);
            FMA2(acc[6][0], a67.x, bl.x); FMA2(acc[6][1], a67.x, bl.y);
            FMA2(acc[6][2], a67.x, bh.x); FMA2(acc[6][3], a67.x, bh.y);
            FMA2(acc[7][0], a67.y, bl.x); FMA2(acc[7][1], a67.y, bl.y);
            FMA2(acc[7][2], a67.y, bh.x); FMA2(acc[7][3], a67.y, bh.y);
        }

        // ---- epilogue per n-tile: scores + running argmax ----
        if (kc == 7) {
            const int nbase = (cc >> 3) << 8;
            const float4 cl = __ldg(reinterpret_cast<const float4*>(&g_cnorm[nbase + 4 * tn]));
            const float4 ch = __ldg(reinterpret_cast<const float4*>(&g_cnorm[nbase + 128 + 4 * tn]));
            #pragma unroll
            for (int i = 0; i < 8; ++i) {
                #pragma unroll
                for (int j = 0; j < 4; ++j) {
                    const int n0 = nbase + ((j & 2) ? 128 : 0) + 4 * tn + ((j & 1) << 1);
                    const float c0 = (j == 0) ? cl.x : (j == 1) ? cl.z : (j == 2) ? ch.x : ch.z;
                    const float c1 = (j == 0) ? cl.y : (j == 1) ? cl.w : (j == 2) ? ch.y : ch.w;
                    const float s0 = u2f_lo(acc[i][j]) - c0;
                    const float s1 = u2f_hi(acc[i][j]) - c1;
                    if (s0 > best[i]) { best[i] = s0; bidx[i] = n0; }
                    if (s1 > best[i]) { best[i] = s1; bidx[i] = n0 + 1; }
                    acc[i][j] = 0ull;
                }
            }
        }
    }
    __syncthreads();

    // ---- cross-thread reduction: 32 candidates/window, alias onto Bs ----
    float* sred = Bs;                      // [m 0..63][cand 0..31]
    int*   sidx = reinterpret_cast<int*>(Bs + 2048);
    int*   widx = reinterpret_cast<int*>(Bs + 4096);
    #pragma unroll
    for (int i = 0; i < 8; ++i) {
        const int m = tm * 8 + i;
        sred[m * 32 + tn] = best[i];
        sidx[m * 32 + tn] = bidx[i];
    }
    __syncthreads();
    if (tid < 64) {
        float bs = sred[tid * 32];
        int   bi = sidx[tid * 32];
        #pragma unroll 8
        for (int q = 1; q < 32; ++q) {
            const float s  = sred[tid * 32 + q];
            const int   ix = sidx[tid * 32 + q];
            if (s > bs || (s == bs && ix < bi)) { bs = s; bi = ix; }
        }
        widx[tid] = bi;
    }
    __syncthreads();

    // ---- gather winning codebook rows (L2-hot) ----
    const float4* cb4  = reinterpret_cast<const float4*>(cb);
    float4*       out4 = reinterpret_cast<float4*>(out) + (size_t)blockIdx.x * (BM * 32);
    #pragma unroll
    for (int i = 0; i < 8; ++i) {
        const int f = i * 256 + tid;
        const int w = f >> 5, c = f & 31;
        out4[f] = __ldg(&cb4[(size_t)widx[w] * 32 + c]);
    }
}

// ---------------------------------------------------------------------------
extern "C" void kernel_launch(void* const* d_in, const int* in_sizes, int n_in,
                              void* d_out, int out_size) {
    const float* ze = (const float*)d_in[0];
    const float* cb = (const float*)d_in[1];
    float* out = (float*)d_out;

    const int M = in_sizes[0] / D;   // 65536
    const int K = in_sizes[1] / D;   // 2048

    const int smem_bytes = 16384 * 4 + 3 * 4096 * 4;   // 112 KB
    cudaFuncSetAttribute(vq_main_kernel, cudaFuncAttributeMaxDynamicSharedMemorySize,
                         smem_bytes);

    cnorm_kernel<<<(K + 7) / 8, NTHR>>>(cb, K);
    transpose_cb_kernel<<<(K * D + NTHR - 1) / NTHR, NTHR>>>(cb, K);
    vq_main_kernel<<<M / BM, NTHR, smem_bytes>>>(ze, cb, out, K);
}

// round 9
// speedup vs baseline: 1.3505x; 1.3287x over previous
#include <cuda_runtime.h>
#include <cuda_bf16.h>
#include <math_constants.h>
#include <cstdint>

// ----------------------------------------------------------------------------
// Window VQ via mma.sync bf16 tensor cores (base ISA, works on sm_100 target).
//   argmin_k ||z - c_k||^2 == argmax_k ( z.c_k - 0.5*||c_k||^2 )
// fp32 emulated as 3-way bf16 split (x = x1+x2+x3); 6 cross-products
// {11,12,21,22,13,31} accumulated in fp32 -> error ~2e-7, exact argmin.
//
// R9 = R8 with the B ldmatrix addressing bug fixed: every lane must provide
// its own row address (base + lane*16); R8 passed a lane-uniform address.
// ----------------------------------------------------------------------------

#define D       128
#define BMW     128     // windows per CTA
#define NTE     64      // codebook entries per staged tile
#define NTHR    256

// smem byte offsets: A 96KB | B0 48KB | B1 48KB | cnorm 8KB = 200KB
#define OFF_A    0
#define OFF_B0   98304
#define OFF_B1   147456
#define OFF_CN   196608
#define SMEM_TOTAL 204800

__device__ float g_cnorm[4096];
// packed B splits: [nt][s 0..2][j 0..7][kt 0..15][r 0..7][c 0..7] bf16, 1.5MB
__device__ __align__(16) __nv_bfloat16 g_Bpk[32 * 3 * 8 * 16 * 64];

// ---------------------------------------------------------------------------
__global__ void cnorm_kernel(const float* __restrict__ cb, int K) {
    int row  = blockIdx.x * 8 + (threadIdx.x >> 5);
    int lane = threadIdx.x & 31;
    if (row < K) {
        const float4 v = reinterpret_cast<const float4*>(cb + (size_t)row * D)[lane];
        float s = v.x * v.x + v.y * v.y + v.z * v.z + v.w * v.w;
        #pragma unroll
        for (int o = 16; o; o >>= 1) s += __shfl_xor_sync(0xffffffffu, s, o);
        if (lane == 0) g_cnorm[row] = 0.5f * s;
    }
}

__device__ __forceinline__ void split3(float x, __nv_bfloat16& h1,
                                       __nv_bfloat16& h2, __nv_bfloat16& h3) {
    h1 = __float2bfloat16(x);
    const float r1 = x - __bfloat162float(h1);
    h2 = __float2bfloat16(r1);
    h3 = __float2bfloat16(r1 - __bfloat162float(h2));
}

// Pack codebook: entry n, dim k -> tile layout per (nt, split, j=n8, kt=k/8):
// 8x8 bf16 tile (row r = n%8, col c = k%8) stored as 128B contiguous.
__global__ void pack_cb_kernel(const float* __restrict__ cb, int K) {
    const int idx = blockIdx.x * NTHR + threadIdx.x;
    if (idx >= K * D) return;
    const int n = idx >> 7, k = idx & 127;
    __nv_bfloat16 h1, h2, h3;
    split3(cb[idx], h1, h2, h3);
    const int nt = n >> 6, j = (n >> 3) & 7, r = n & 7;
    const int kt = k >> 3, c = k & 7;
    const size_t off = (size_t)nt * 24576 + j * 1024 + kt * 64 + r * 8 + c;
    g_Bpk[off]         = h1;
    g_Bpk[off + 8192]  = h2;
    g_Bpk[off + 16384] = h3;
}

// ---------------------------------------------------------------------------
#define LDSM4(r0, r1, r2, r3, a) \
    asm volatile("ldmatrix.sync.aligned.m8n8.x4.shared.b16 {%0,%1,%2,%3}, [%4];" \
                 : "=r"(r0), "=r"(r1), "=r"(r2), "=r"(r3) : "r"(a))

#define MMA(ac, A0, A1, A2, A3, B0, B1) \
    asm volatile("mma.sync.aligned.m16n8k16.row.col.f32.bf16.bf16.f32 " \
                 "{%0,%1,%2,%3},{%4,%5,%6,%7},{%8,%9},{%0,%1,%2,%3};" \
                 : "+f"(ac[0]), "+f"(ac[1]), "+f"(ac[2]), "+f"(ac[3]) \
                 : "r"(A0), "r"(A1), "r"(A2), "r"(A3), "r"(B0), "r"(B1))

__device__ __forceinline__ uint32_t smem_u32(const void* p) {
    uint32_t a;
    asm("{ .reg .u64 t; cvta.to.shared.u64 t, %1; cvt.u32.u64 %0, t; }" : "=r"(a) : "l"(p));
    return a;
}
__device__ __forceinline__ void cp_async16(uint32_t saddr, const void* g) {
    asm volatile("cp.async.cg.shared.global [%0], [%1], 16;" :: "r"(saddr), "l"(g));
}

// load 8 k-step B fragments (16 regs) for one n8 region (2KB of tiles).
// addr MUST already include lane*16 (per-lane row address for ldmatrix).
__device__ __forceinline__ void load_bfrags(uint32_t* b, uint32_t addr) {
    #pragma unroll
    for (int q = 0; q < 4; ++q)
        LDSM4(b[q * 4 + 0], b[q * 4 + 1], b[q * 4 + 2], b[q * 4 + 3], addr + q * 512);
}

// one split-pair pass: 8 k-steps x 2 n8 accumulators
__device__ __forceinline__ void mma_pass(float (*acc)[4], const uint32_t (*af)[4],
                                         const uint32_t* b0, const uint32_t* b1) {
    #pragma unroll
    for (int kk = 0; kk < 8; ++kk) {
        const int bi = 2 * kk;
        MMA(acc[0], af[kk][0], af[kk][1], af[kk][2], af[kk][3], b0[bi], b0[bi + 1]);
        MMA(acc[1], af[kk][0], af[kk][1], af[kk][2], af[kk][3], b1[bi], b1[bi + 1]);
    }
}

// ---------------------------------------------------------------------------
__global__ __launch_bounds__(NTHR, 1)
void vq_mma_kernel(const float* __restrict__ ze,
                   const float* __restrict__ cb,
                   float* __restrict__ out,
                   int ntiles) {
    extern __shared__ __align__(16) char smem[];
    float* Cn = reinterpret_cast<float*>(smem + OFF_CN);

    const uint32_t sbase = smem_u32(smem);
    const int tid  = threadIdx.x;
    const int w    = tid >> 5;
    const int lane = tid & 31;

    // ---- 1. build A split tiles in smem (ldmatrix-packed, mma subtile order) ----
    {
        const float* zsrc = ze + (size_t)blockIdx.x * (BMW * D);
        for (int i = tid; i < BMW * D; i += NTHR) {
            const int m = i >> 7, k = i & 127;
            __nv_bfloat16 h1, h2, h3;
            split3(zsrc[i], h1, h2, h3);
            const int t = ((m >> 3) & 1) | (((k >> 3) & 1) << 1);
            const int base = (m >> 4) * 12288 + (k >> 4) * 512 + t * 128
                           + (m & 7) * 16 + (k & 7) * 2;
            *reinterpret_cast<__nv_bfloat16*>(smem + base)        = h1;
            *reinterpret_cast<__nv_bfloat16*>(smem + base + 4096) = h2;
            *reinterpret_cast<__nv_bfloat16*>(smem + base + 8192) = h3;
        }
        for (int i = tid; i < ntiles * NTE; i += NTHR) Cn[i] = g_cnorm[i];
    }
    __syncthreads();

    // ---- 2. A1/A2 fragments resident in registers ----
    uint32_t a1f[8][4], a2f[8][4];
    const uint32_t abase = sbase + w * 12288 + lane * 16;
    #pragma unroll
    for (int kk = 0; kk < 8; ++kk)
        LDSM4(a1f[kk][0], a1f[kk][1], a1f[kk][2], a1f[kk][3], abase + kk * 512);
    #pragma unroll
    for (int kk = 0; kk < 8; ++kk)
        LDSM4(a2f[kk][0], a2f[kk][1], a2f[kk][2], a2f[kk][3], abase + 4096 + kk * 512);

    // ---- 3. prologue: stage B tile 0 ----
    {
        const char* src = reinterpret_cast<const char*>(g_Bpk);
        #pragma unroll
        for (int u = 0; u < 12; ++u)
            cp_async16(sbase + OFF_B0 + u * 4096 + tid * 16, src + u * 4096 + tid * 16);
        asm volatile("cp.async.commit_group;");
    }

    float best[2] = {-CUDART_INF_F, -CUDART_INF_F};
    int   bidx[2] = {0, 0};

    for (int nt = 0; nt < ntiles; ++nt) {
        asm volatile("cp.async.wait_group 0;");
        __syncthreads();

        if (nt + 1 < ntiles) {
            const char* src = reinterpret_cast<const char*>(g_Bpk) + (size_t)(nt + 1) * 49152;
            const uint32_t dst = sbase + (((nt + 1) & 1) ? OFF_B1 : OFF_B0);
            #pragma unroll
            for (int u = 0; u < 12; ++u)
                cp_async16(dst + u * 4096 + tid * 16, src + u * 4096 + tid * 16);
            asm volatile("cp.async.commit_group;");
        }

        // per-lane base inside the current B buffer (FIX: + lane*16)
        const uint32_t bb = sbase + ((nt & 1) ? OFF_B1 : OFF_B0) + lane * 16;
        const int ntbase = nt * NTE;

        #pragma unroll
        for (int jj = 0; jj < 4; ++jj) {
            float acc[2][4] = {{0.f, 0.f, 0.f, 0.f}, {0.f, 0.f, 0.f, 0.f}};
            uint32_t b0r[16], b1r[16];

            // split s=0 of B: pairs (A1,B1), (A2,B1), (A3,B1)
            load_bfrags(b0r, bb + (2 * jj) * 2048);
            load_bfrags(b1r, bb + (2 * jj + 1) * 2048);
            mma_pass(acc, a1f, b0r, b1r);
            mma_pass(acc, a2f, b0r, b1r);
            #pragma unroll
            for (int kk = 0; kk < 8; ++kk) {     // A3 from smem
                uint32_t t0, t1, t2, t3;
                LDSM4(t0, t1, t2, t3, abase + 8192 + kk * 512);
                MMA(acc[0], t0, t1, t2, t3, b0r[2 * kk], b0r[2 * kk + 1]);
                MMA(acc[1], t0, t1, t2, t3, b1r[2 * kk], b1r[2 * kk + 1]);
            }

            // split s=1 of B: pairs (A1,B2), (A2,B2)
            load_bfrags(b0r, bb + 16384 + (2 * jj) * 2048);
            load_bfrags(b1r, bb + 16384 + (2 * jj + 1) * 2048);
            mma_pass(acc, a1f, b0r, b1r);
            mma_pass(acc, a2f, b0r, b1r);

            // split s=2 of B: pair (A1,B3)
            load_bfrags(b0r, bb + 32768 + (2 * jj) * 2048);
            load_bfrags(b1r, bb + 32768 + (2 * jj + 1) * 2048);
            mma_pass(acc, a1f, b0r, b1r);

            // ---- epilogue: scores + running argmax (ascending n) ----
            #pragma unroll
            for (int js = 0; js < 2; ++js) {
                const int n0 = ntbase + (2 * jj + js) * 8 + 2 * (lane & 3);
                const float2 cn2 = *reinterpret_cast<const float2*>(&Cn[n0]);
                const float s00 = acc[js][0] - cn2.x;   // row g,    n0
                const float s01 = acc[js][1] - cn2.y;   // row g,    n0+1
                const float s10 = acc[js][2] - cn2.x;   // row g+8,  n0
                const float s11 = acc[js][3] - cn2.y;
                if (s00 > best[0]) { best[0] = s00; bidx[0] = n0; }
                if (s01 > best[0]) { best[0] = s01; bidx[0] = n0 + 1; }
                if (s10 > best[1]) { best[1] = s10; bidx[1] = n0; }
                if (s11 > best[1]) { best[1] = s11; bidx[1] = n0 + 1; }
            }
        }
    }

    // ---- reduce 4 candidates per window (lanes l%4), reuse B0 region ----
    float* sF   = reinterpret_cast<float*>(smem + OFF_B0);         // [128][4]
    int*   sI   = reinterpret_cast<int*>(smem + OFF_B0 + 2048);
    int*   widx = reinterpret_cast<int*>(smem + OFF_B0 + 4096);
    __syncthreads();      // all warps done reading B buffers
    {
        const int m0 = 16 * w + (lane >> 2);
        const int q  = lane & 3;
        sF[m0 * 4 + q] = best[0];  sI[m0 * 4 + q] = bidx[0];
        sF[(m0 + 8) * 4 + q] = best[1];  sI[(m0 + 8) * 4 + q] = bidx[1];
    }
    __syncthreads();
    if (tid < BMW) {
        float bs = sF[tid * 4];
        int   bi = sI[tid * 4];
        #pragma unroll
        for (int q = 1; q < 4; ++q) {
            const float s  = sF[tid * 4 + q];
            const int   ix = sI[tid * 4 + q];
            if (s > bs || (s == bs && ix < bi)) { bs = s; bi = ix; }
        }
        widx[tid] = bi;
    }
    __syncthreads();

    // ---- gather winning codebook rows (L2-hot) ----
    const float4* cb4  = reinterpret_cast<const float4*>(cb);
    float4*       out4 = reinterpret_cast<float4*>(out) + (size_t)blockIdx.x * (BMW * 32);
    #pragma unroll
    for (int i = 0; i < 16; ++i) {
        const int f = i * 256 + tid;          // 0..4095
        const int wv = f >> 5, c = f & 31;
        out4[f] = __ldg(&cb4[(size_t)widx[wv] * 32 + c]);
    }
}

// ---------------------------------------------------------------------------
extern "C" void kernel_launch(void* const* d_in, const int* in_sizes, int n_in,
                              void* d_out, int out_size) {
    const float* ze = (const float*)d_in[0];
    const float* cb = (const float*)d_in[1];
    float* out = (float*)d_out;

    const int M = in_sizes[0] / D;   // 65536
    const int K = in_sizes[1] / D;   // 2048

    cudaFuncSetAttribute(vq_mma_kernel, cudaFuncAttributeMaxDynamicSharedMemorySize,
                         SMEM_TOTAL);

    cnorm_kernel<<<(K + 7) / 8, NTHR>>>(cb, K);
    pack_cb_kernel<<<(K * D + NTHR - 1) / NTHR, NTHR>>>(cb, K);
    vq_mma_kernel<<<M / BMW, NTHR, SMEM_TOTAL>>>(ze, cb, out, K / NTE);
}